// round 4
// baseline (speedup 1.0000x reference)
#include <cuda_runtime.h>
#include <cuda_bf16.h>
#include <cstdint>

#define NNODE 50000
#define NEDGE 800000
#define H 128
#define LNUM 4
#define HPAD 50048            // 391 * 128
#define NPADC 53248           // 13 * 4096, padded counts for int4 scan
#define BN_EPS 1e-5f

// ---------------- device scratch (allocation-free rule: __device__ globals) ---
__device__ int   g_counts[NPADC];      // pad tail beyond NNODE stays 0 forever
__device__ int   g_cursor[NNODE];
__device__ int   g_offs[NNODE + 1];
__device__ int   g_ssrc[NEDGE];
__device__ float g_t1[(size_t)HPAD * H];
__device__ float g_t2[(size_t)HPAD * H];
__device__ float g_accs[8 * H];        // per-producer-GEMM stats slots
__device__ float g_accq[8 * H];

// ---------------- helpers ----------------------------------------------------
__device__ __forceinline__ float4 f4zero() { return make_float4(0.f, 0.f, 0.f, 0.f); }
__device__ __forceinline__ void f4add(float4& a, const float4 b) {
    a.x += b.x; a.y += b.y; a.z += b.z; a.w += b.w;
}
__device__ __forceinline__ float4 f4affine_relu(float4 v, float4 a, float4 s) {
    float4 r;
    r.x = fmaxf(fmaf(a.x, v.x, s.x), 0.f);
    r.y = fmaxf(fmaf(a.y, v.y, s.y), 0.f);
    r.z = fmaxf(fmaf(a.z, v.z, s.z), 0.f);
    r.w = fmaxf(fmaf(a.w, v.w, s.w), 0.f);
    return r;
}
// split fp32 -> (bf16 hi | bf16 lo) packed in one 32-bit word (lo in high half)
__device__ __forceinline__ uint32_t pack_split(float v) {
    __nv_bfloat16 h = __float2bfloat16(v);
    float hf = __bfloat162float(h);
    __nv_bfloat16 l = __float2bfloat16(v - hf);
    return (uint32_t)__bfloat16_as_ushort(h) | ((uint32_t)__bfloat16_as_ushort(l) << 16);
}
__device__ __forceinline__ uint4 pack_split4(float4 v) {
    return make_uint4(pack_split(v.x), pack_split(v.y), pack_split(v.z), pack_split(v.w));
}
__device__ __forceinline__ void mma_bf16(float d[4], const uint32_t a[4],
                                         uint32_t b0, uint32_t b1) {
    asm volatile(
        "mma.sync.aligned.m16n8k16.row.col.f32.bf16.bf16.f32 "
        "{%0,%1,%2,%3}, {%4,%5,%6,%7}, {%8,%9}, {%0,%1,%2,%3};\n"
        : "+f"(d[0]), "+f"(d[1]), "+f"(d[2]), "+f"(d[3])
        : "r"(a[0]), "r"(a[1]), "r"(a[2]), "r"(a[3]), "r"(b0), "r"(b1));
}

// Inline BN-affine coefficient computation from a stats slot.
// CTYPE 1: relu(bn1(y + fc1_b)) -> a = g*rsqrt(var), s = b - mu*a  (fc bias cancels)
// CTYPE 2: relu(bn3(bn2(y + fc2_b))) -> composed analytically (b2, bn2_b cancel)
template <int CTYPE>
__device__ __forceinline__ void coef_from_slot(int t, int slot,
                                               const float* __restrict__ p0,
                                               const float* __restrict__ p1,
                                               const float* __restrict__ p2,
                                               float* ta_s, float* ts_s) {
    if (t < 128) {
        float mu = g_accs[slot * H + t] * (1.f / NNODE);
        float var = g_accq[slot * H + t] * (1.f / NNODE) - mu * mu;
        if (CTYPE == 1) {
            float a = p0[t] * rsqrtf(var + BN_EPS);
            ta_s[t] = a;
            ts_s[t] = p1[t] - mu * a;
        } else {
            float r2 = rsqrtf(var + BN_EPS);
            float gr = p0[t] * r2;
            float v3 = gr * gr * var;
            float A = gr * p1[t] * rsqrtf(v3 + BN_EPS);
            ta_s[t] = A;
            ts_s[t] = p2[t] - mu * A;
        }
    }
}

// ---------------- CSR build ---------------------------------------------------
__global__ void zero_k() {
    int i = blockIdx.x * blockDim.x + threadIdx.x;
    if (i < NNODE) g_counts[i] = 0;
    if (i < 8 * H) { g_accs[i] = 0.f; g_accq[i] = 0.f; }
}

__global__ void hist_k(const int* __restrict__ dst) {
    int e = blockIdx.x * blockDim.x + threadIdx.x;
    if (e < NEDGE) atomicAdd(&g_counts[dst[e]], 1);
}

// 1024-thread single-block scan, int4 per thread per iteration (13 iterations).
__global__ void scan_k() {
    __shared__ int wsum[32];
    __shared__ int carry_s;
    int t = threadIdx.x;
    int lane = t & 31;
    if (t == 0) carry_s = 0;
    __syncthreads();
    #pragma unroll 1
    for (int it = 0; it < NPADC / 4096; ++it) {
        int i4 = it * 4096 + t * 4;
        int4 c = *(const int4*)(g_counts + i4);   // pad region is always 0
        int s0 = c.x, s1 = s0 + c.y, s2 = s1 + c.z, s3 = s2 + c.w;
        int x = s3;
        #pragma unroll
        for (int d = 1; d < 32; d <<= 1) {
            int y = __shfl_up_sync(0xffffffffu, x, d);
            if (lane >= d) x += y;
        }
        if (lane == 31) wsum[t >> 5] = x;
        __syncthreads();
        if (t < 32) {
            int y = wsum[t];
            #pragma unroll
            for (int d = 1; d < 32; d <<= 1) {
                int z = __shfl_up_sync(0xffffffffu, y, d);
                if (t >= d) y += z;
            }
            wsum[t] = y;
        }
        __syncthreads();
        int base = carry_s + ((t >= 32) ? wsum[(t >> 5) - 1] : 0) + x - s3;
        if (i4 + 0 < NNODE) { g_offs[i4 + 0] = base;      g_cursor[i4 + 0] = base; }
        if (i4 + 1 < NNODE) { g_offs[i4 + 1] = base + s0; g_cursor[i4 + 1] = base + s0; }
        if (i4 + 2 < NNODE) { g_offs[i4 + 2] = base + s1; g_cursor[i4 + 2] = base + s1; }
        if (i4 + 3 < NNODE) { g_offs[i4 + 3] = base + s2; g_cursor[i4 + 3] = base + s2; }
        int tot = wsum[31];
        __syncthreads();
        if (t == 0) carry_s += tot;
        __syncthreads();
    }
    if (t == 0) g_offs[NNODE] = NEDGE;
}

__global__ void fill_k(const int* __restrict__ ei) {
    int e = blockIdx.x * blockDim.x + threadIdx.x;
    if (e < NEDGE) {
        int d = ei[NEDGE + e];          // dst row of edge_index [2, E]
        int pos = atomicAdd(&g_cursor[d], 1);
        g_ssrc[pos] = ei[e];            // src
    }
}

// ---------------- shared GEMM tile constants ----------------------------------
#define SMP 136   // word pitch: conflict-free LDS.64 / STS.128 patterns
#define GEMM_SMEM_BYTES (2 * 128 * SMP * 4 + 256 * 4)

// MMA mainloop + stats + store, shared by both GEMM kernels.
// As/Ws hold packed (hi|lo) bf16 pairs, 128x128, K fully resident.
template <bool STATS, bool BIAS>
__device__ __forceinline__ void mma_core(uint32_t* sm, float* out,
                                         const float* __restrict__ bias,
                                         int m0, int storeN, int slot_out) {
    uint32_t* As = sm;
    uint32_t* Ws = sm + 128 * SMP;
    int t = threadIdx.x;
    int lane = t & 31;
    int w = t >> 5;
    int wm = w & 3;          // m-warp 0..3
    int wn = w >> 2;         // n-warp 0..1
    int g = lane >> 2;
    int tig = lane & 3;
    int mb = wm * 32;
    int nb = wn * 64;

    float d[2][8][4];
    #pragma unroll
    for (int mt = 0; mt < 2; ++mt)
        #pragma unroll
        for (int nt = 0; nt < 8; ++nt)
            #pragma unroll
            for (int i = 0; i < 4; ++i) d[mt][nt][i] = 0.f;

    #pragma unroll
    for (int ks = 0; ks < 8; ++ks) {
        int k0 = ks * 16;
        uint32_t ah[2][4], al[2][4];
        #pragma unroll
        for (int mt = 0; mt < 2; ++mt) {
            int r0 = mb + mt * 16 + g;
            uint2 w0 = *(const uint2*)(As + r0 * SMP + k0 + 2 * tig);
            uint2 w1 = *(const uint2*)(As + (r0 + 8) * SMP + k0 + 2 * tig);
            uint2 w2 = *(const uint2*)(As + r0 * SMP + k0 + 8 + 2 * tig);
            uint2 w3 = *(const uint2*)(As + (r0 + 8) * SMP + k0 + 8 + 2 * tig);
            ah[mt][0] = __byte_perm(w0.x, w0.y, 0x5410); al[mt][0] = __byte_perm(w0.x, w0.y, 0x7632);
            ah[mt][1] = __byte_perm(w1.x, w1.y, 0x5410); al[mt][1] = __byte_perm(w1.x, w1.y, 0x7632);
            ah[mt][2] = __byte_perm(w2.x, w2.y, 0x5410); al[mt][2] = __byte_perm(w2.x, w2.y, 0x7632);
            ah[mt][3] = __byte_perm(w3.x, w3.y, 0x5410); al[mt][3] = __byte_perm(w3.x, w3.y, 0x7632);
        }
        #pragma unroll
        for (int nt = 0; nt < 8; ++nt) {
            int o = nb + nt * 8 + g;
            uint2 u0 = *(const uint2*)(Ws + o * SMP + k0 + 2 * tig);
            uint2 u1 = *(const uint2*)(Ws + o * SMP + k0 + 8 + 2 * tig);
            uint32_t bh0 = __byte_perm(u0.x, u0.y, 0x5410);
            uint32_t bl0 = __byte_perm(u0.x, u0.y, 0x7632);
            uint32_t bh1 = __byte_perm(u1.x, u1.y, 0x5410);
            uint32_t bl1 = __byte_perm(u1.x, u1.y, 0x7632);
            #pragma unroll
            for (int mt = 0; mt < 2; ++mt) {
                mma_bf16(d[mt][nt], ah[mt], bh0, bh1);   // hi*hi
                mma_bf16(d[mt][nt], al[mt], bh0, bh1);   // lo*hi
                mma_bf16(d[mt][nt], ah[mt], bl0, bl1);   // hi*lo
            }
        }
    }

    if (STATS) {
        float s[8][2], q[8][2];
        #pragma unroll
        for (int nt = 0; nt < 8; ++nt)
            #pragma unroll
            for (int j = 0; j < 2; ++j) {
                float sv = 0.f, qv = 0.f;
                #pragma unroll
                for (int mt = 0; mt < 2; ++mt) {
                    float v0 = d[mt][nt][j], v1 = d[mt][nt][j + 2];
                    sv += v0 + v1;
                    qv = fmaf(v0, v0, fmaf(v1, v1, qv));
                }
                #pragma unroll
                for (int off = 4; off < 32; off <<= 1) {
                    sv += __shfl_xor_sync(0xffffffffu, sv, off);
                    qv += __shfl_xor_sync(0xffffffffu, qv, off);
                }
                s[nt][j] = sv; q[nt][j] = qv;
            }
        __syncthreads();                      // done reading As/Ws; reuse as Red
        float* RedS = (float*)sm;             // [8][64]
        float* RedQ = (float*)sm + 512;       // [8][64]
        if (g == 0) {
            #pragma unroll
            for (int nt = 0; nt < 8; ++nt)
                #pragma unroll
                for (int j = 0; j < 2; ++j) {
                    int lc = nt * 8 + tig * 2 + j;
                    RedS[w * 64 + lc] = s[nt][j];
                    RedQ[w * 64 + lc] = q[nt][j];
                }
        }
        __syncthreads();
        if (t < 128) {
            int gsel = t >> 6;
            int lc = t & 63;
            float sv = 0.f, qv = 0.f;
            #pragma unroll
            for (int ww = 0; ww < 4; ++ww) {
                sv += RedS[(gsel * 4 + ww) * 64 + lc];
                qv += RedQ[(gsel * 4 + ww) * 64 + lc];
            }
            atomicAdd(&g_accs[slot_out * H + gsel * 64 + lc], sv);
            atomicAdd(&g_accq[slot_out * H + gsel * 64 + lc], qv);
        }
    }

    #pragma unroll
    for (int nt = 0; nt < 8; ++nt) {
        int col = nb + nt * 8 + tig * 2;
        float2 bb = make_float2(0.f, 0.f);
        if (BIAS) bb = *(const float2*)(bias + col);
        #pragma unroll
        for (int mt = 0; mt < 2; ++mt) {
            int r0 = m0 + mb + mt * 16 + g;
            if (r0 < storeN) {
                float2 v = make_float2(d[mt][nt][0] + bb.x, d[mt][nt][1] + bb.y);
                *(float2*)(out + (size_t)r0 * H + col) = v;
            }
            if (r0 + 8 < storeN) {
                float2 v = make_float2(d[mt][nt][2] + bb.x, d[mt][nt][3] + bb.y);
                *(float2*)(out + (size_t)(r0 + 8) * H + col) = v;
            }
        }
    }
}

// ---------------- fused aggregation + GEMM1 + stats ---------------------------
// A-tile = gather:  h_v = T(x_v) + sum_{j in N(v)} T(x_j), built directly in smem.
// T = identity (layer 0) or composed bn2/bn3 affine+relu from slot_in (CTYPE 2).
// Output: g_t1 = h @ fc1_w^T, stats -> slot_out.
template <bool TRANS>
__global__ __launch_bounds__(256, 1) void gemm_ag(
    const float* __restrict__ xext, const float* __restrict__ W,
    int slot_in, int slot_out,
    const float* __restrict__ p0, const float* __restrict__ p1,
    const float* __restrict__ p2) {
    const float* in = TRANS ? (const float*)g_t2 : xext;
    extern __shared__ uint32_t sm[];
    uint32_t* As = sm;
    uint32_t* Ws = sm + 128 * SMP;
    float* ta_s = (float*)(sm + 2 * 128 * SMP);
    float* ts_s = ta_s + 128;

    int t = threadIdx.x;
    int m0 = blockIdx.x * 128;

    if (TRANS) {
        coef_from_slot<2>(t, slot_in, p0, p1, p2, ta_s, ts_s);
        __syncthreads();
    }

    // W fill (each thread 16 float4s, split-packed)
    #pragma unroll
    for (int j = 0; j < 16; ++j) {
        int idx = t + j * 256;
        int row = idx >> 5, q = idx & 31;
        float4 wv = *(const float4*)(W + (size_t)row * H + q * 4);
        *(uint4*)(Ws + row * SMP + q * 4) = pack_split4(wv);
    }

    // A fill via CSR gather: warp w handles rows w*16 .. w*16+15
    {
        int lane = t & 31;
        int w = t >> 5;
        int cb = lane * 4;
        float4 Aa = f4zero(), Ss = f4zero();
        if (TRANS) {
            Aa = *(const float4*)(ta_s + cb);
            Ss = *(const float4*)(ts_s + cb);
        }
        #pragma unroll 1
        for (int rr = 0; rr < 16; ++rr) {
            int row = w * 16 + rr;
            int gr = m0 + row;
            float4 a0 = f4zero(), a1 = f4zero(), a2 = f4zero(), a3 = f4zero();
            if (gr < NNODE) {
                float4 v = *(const float4*)(in + (size_t)gr * H + cb);
                a0 = TRANS ? f4affine_relu(v, Aa, Ss) : v;
                int j = g_offs[gr];
                int jend = g_offs[gr + 1];
                for (; j + 7 < jend; j += 8) {
                    int s0 = g_ssrc[j + 0], s1 = g_ssrc[j + 1];
                    int s2 = g_ssrc[j + 2], s3 = g_ssrc[j + 3];
                    int s4 = g_ssrc[j + 4], s5 = g_ssrc[j + 5];
                    int s6 = g_ssrc[j + 6], s7 = g_ssrc[j + 7];
                    float4 v0 = *(const float4*)(in + (size_t)s0 * H + cb);
                    float4 v1 = *(const float4*)(in + (size_t)s1 * H + cb);
                    float4 v2 = *(const float4*)(in + (size_t)s2 * H + cb);
                    float4 v3 = *(const float4*)(in + (size_t)s3 * H + cb);
                    float4 v4 = *(const float4*)(in + (size_t)s4 * H + cb);
                    float4 v5 = *(const float4*)(in + (size_t)s5 * H + cb);
                    float4 v6 = *(const float4*)(in + (size_t)s6 * H + cb);
                    float4 v7 = *(const float4*)(in + (size_t)s7 * H + cb);
                    if (TRANS) {
                        v0 = f4affine_relu(v0, Aa, Ss); v1 = f4affine_relu(v1, Aa, Ss);
                        v2 = f4affine_relu(v2, Aa, Ss); v3 = f4affine_relu(v3, Aa, Ss);
                        v4 = f4affine_relu(v4, Aa, Ss); v5 = f4affine_relu(v5, Aa, Ss);
                        v6 = f4affine_relu(v6, Aa, Ss); v7 = f4affine_relu(v7, Aa, Ss);
                    }
                    f4add(a0, v0); f4add(a1, v1); f4add(a2, v2); f4add(a3, v3);
                    f4add(a0, v4); f4add(a1, v5); f4add(a2, v6); f4add(a3, v7);
                }
                for (; j + 3 < jend; j += 4) {
                    int s0 = g_ssrc[j + 0], s1 = g_ssrc[j + 1];
                    int s2 = g_ssrc[j + 2], s3 = g_ssrc[j + 3];
                    float4 v0 = *(const float4*)(in + (size_t)s0 * H + cb);
                    float4 v1 = *(const float4*)(in + (size_t)s1 * H + cb);
                    float4 v2 = *(const float4*)(in + (size_t)s2 * H + cb);
                    float4 v3 = *(const float4*)(in + (size_t)s3 * H + cb);
                    if (TRANS) {
                        v0 = f4affine_relu(v0, Aa, Ss); v1 = f4affine_relu(v1, Aa, Ss);
                        v2 = f4affine_relu(v2, Aa, Ss); v3 = f4affine_relu(v3, Aa, Ss);
                    }
                    f4add(a0, v0); f4add(a1, v1); f4add(a2, v2); f4add(a3, v3);
                }
                for (; j < jend; ++j) {
                    float4 v = *(const float4*)(in + (size_t)g_ssrc[j] * H + cb);
                    if (TRANS) v = f4affine_relu(v, Aa, Ss);
                    f4add(a0, v);
                }
                f4add(a0, a1); f4add(a2, a3); f4add(a0, a2);
            }
            *(uint4*)(As + row * SMP + cb) = pack_split4(a0);
        }
    }
    __syncthreads();

    mma_core<true, false>(sm, g_t1, nullptr, m0, HPAD, slot_out);
}

// ---------------- plain GEMM (A from g_t1 or g_t2) ----------------------------
// CTYPE 1: A = relu(bn1-affine(g_t1)) from slot_in  (gemm2 path, out = g_t2)
// CTYPE 2: A = relu(bn3∘bn2-affine(g_t2)) from slot_in (final classifier, out = ext)
template <int CTYPE, bool STATS, bool BIAS>
__global__ __launch_bounds__(256, 1) void gemm_tc(
    int asel, const float* __restrict__ W, float* __restrict__ oext,
    int slot_in, int slot_out,
    const float* __restrict__ p0, const float* __restrict__ p1,
    const float* __restrict__ p2,
    const float* __restrict__ bias, int storeN) {
    const float* A = (asel == 1) ? g_t1 : g_t2;
    float* out = (oext != nullptr) ? oext : g_t2;

    extern __shared__ uint32_t sm[];
    uint32_t* As = sm;
    uint32_t* Ws = sm + 128 * SMP;
    float* ta_s = (float*)(sm + 2 * 128 * SMP);
    float* ts_s = ta_s + 128;

    int t = threadIdx.x;
    int m0 = blockIdx.x * 128;

    coef_from_slot<CTYPE>(t, slot_in, p0, p1, p2, ta_s, ts_s);
    __syncthreads();

    #pragma unroll
    for (int j = 0; j < 16; ++j) {
        int idx = t + j * 256;
        int row = idx >> 5, q = idx & 31;
        int gr = m0 + row;
        float4 v = f4zero();
        if (gr < NNODE) {
            v = *(const float4*)(A + (size_t)gr * H + q * 4);
            float4 a4 = *(const float4*)(ta_s + q * 4);
            float4 s4 = *(const float4*)(ts_s + q * 4);
            v = f4affine_relu(v, a4, s4);
        }
        *(uint4*)(As + row * SMP + q * 4) = pack_split4(v);

        float4 wv = *(const float4*)(W + (size_t)row * H + q * 4);
        *(uint4*)(Ws + row * SMP + q * 4) = pack_split4(wv);
    }
    __syncthreads();

    mma_core<STATS, BIAS>(sm, out, bias, m0, storeN, slot_out);
}

// ---------------- launch ------------------------------------------------------
extern "C" void kernel_launch(void* const* d_in, const int* in_sizes, int n_in,
                              void* d_out, int out_size) {
    const float* x     = (const float*)d_in[0];
    const int*   ei    = (const int*)  d_in[1];
    const float* fc1_w = (const float*)d_in[2];
    const float* bn1_g = (const float*)d_in[4];
    const float* bn1_b = (const float*)d_in[5];
    const float* fc2_w = (const float*)d_in[6];
    const float* bn2_g = (const float*)d_in[8];
    const float* bn3_g = (const float*)d_in[10];
    const float* bn3_b = (const float*)d_in[11];
    const float* fc_w  = (const float*)d_in[12];
    const float* fc_b  = (const float*)d_in[13];
    float* out = (float*)d_out;

    cudaFuncSetAttribute(gemm_ag<false>,
                         cudaFuncAttributeMaxDynamicSharedMemorySize, GEMM_SMEM_BYTES);
    cudaFuncSetAttribute(gemm_ag<true>,
                         cudaFuncAttributeMaxDynamicSharedMemorySize, GEMM_SMEM_BYTES);
    cudaFuncSetAttribute(gemm_tc<1, true,  false>,
                         cudaFuncAttributeMaxDynamicSharedMemorySize, GEMM_SMEM_BYTES);
    cudaFuncSetAttribute(gemm_tc<2, false, true >,
                         cudaFuncAttributeMaxDynamicSharedMemorySize, GEMM_SMEM_BYTES);

    zero_k<<<(NNODE + 255) / 256, 256>>>();
    hist_k<<<(NEDGE + 255) / 256, 256>>>(ei + NEDGE);
    scan_k<<<1, 1024>>>();
    fill_k<<<(NEDGE + 255) / 256, 256>>>(ei);

    const int GEMM_GRID = HPAD / 128;   // 391

    for (int i = 0; i < LNUM; ++i) {
        if (i == 0)
            gemm_ag<false><<<GEMM_GRID, 256, GEMM_SMEM_BYTES>>>(
                x, fc1_w, -1, 0, nullptr, nullptr, nullptr);
        else
            gemm_ag<true><<<GEMM_GRID, 256, GEMM_SMEM_BYTES>>>(
                nullptr, fc1_w + (size_t)i * H * H, 2 * i - 1, 2 * i,
                bn2_g + (i - 1) * H, bn3_g + (i - 1) * H, bn3_b + (i - 1) * H);
        gemm_tc<1, true, false><<<GEMM_GRID, 256, GEMM_SMEM_BYTES>>>(
            1, fc2_w + (size_t)i * H * H, nullptr, 2 * i, 2 * i + 1,
            bn1_g + i * H, bn1_b + i * H, nullptr, nullptr, HPAD);
    }
    gemm_tc<2, false, true><<<GEMM_GRID, 256, GEMM_SMEM_BYTES>>>(
        2, fc_w, out, 7, -1,
        bn2_g + 3 * H, bn3_g + 3 * H, bn3_b + 3 * H, fc_b, NNODE);
}

// round 5
// speedup vs baseline: 1.2712x; 1.2712x over previous
#include <cuda_runtime.h>
#include <cuda_bf16.h>
#include <cstdint>

#define NNODE 50000
#define NEDGE 800000
#define H 128
#define LNUM 4
#define HPAD 50048            // 391 * 128
#define NPADC 53248           // 13 * 4096, padded counts for int4 scan
#define BN_EPS 1e-5f

// ---------------- device scratch (allocation-free rule: __device__ globals) ---
__device__ int   g_counts[NPADC];      // pad tail beyond NNODE stays 0 forever
__device__ int   g_cursor[NNODE];
__device__ int   g_offs[NNODE + 1];
__device__ int   g_ssrc[NEDGE];
__device__ float g_h [(size_t)HPAD * H];
__device__ float g_t1[(size_t)HPAD * H];
__device__ float g_t2[(size_t)HPAD * H];
__device__ float g_accs[8 * H];        // per-producer-GEMM stats slots
__device__ float g_accq[8 * H];

// ---------------- helpers ----------------------------------------------------
__device__ __forceinline__ float4 f4zero() { return make_float4(0.f, 0.f, 0.f, 0.f); }
__device__ __forceinline__ void f4add(float4& a, const float4 b) {
    a.x += b.x; a.y += b.y; a.z += b.z; a.w += b.w;
}
__device__ __forceinline__ float4 f4affine_relu(float4 v, float4 a, float4 s) {
    float4 r;
    r.x = fmaxf(fmaf(a.x, v.x, s.x), 0.f);
    r.y = fmaxf(fmaf(a.y, v.y, s.y), 0.f);
    r.z = fmaxf(fmaf(a.z, v.z, s.z), 0.f);
    r.w = fmaxf(fmaf(a.w, v.w, s.w), 0.f);
    return r;
}
// split fp32 -> (bf16 hi | bf16 lo) packed in one 32-bit word (lo in high half)
__device__ __forceinline__ uint32_t pack_split(float v) {
    __nv_bfloat16 h = __float2bfloat16(v);
    float hf = __bfloat162float(h);
    __nv_bfloat16 l = __float2bfloat16(v - hf);
    return (uint32_t)__bfloat16_as_ushort(h) | ((uint32_t)__bfloat16_as_ushort(l) << 16);
}
__device__ __forceinline__ uint4 pack_split4(float4 v) {
    return make_uint4(pack_split(v.x), pack_split(v.y), pack_split(v.z), pack_split(v.w));
}
__device__ __forceinline__ void mma_bf16(float d[4], const uint32_t a[4],
                                         uint32_t b0, uint32_t b1) {
    asm volatile(
        "mma.sync.aligned.m16n8k16.row.col.f32.bf16.bf16.f32 "
        "{%0,%1,%2,%3}, {%4,%5,%6,%7}, {%8,%9}, {%0,%1,%2,%3};\n"
        : "+f"(d[0]), "+f"(d[1]), "+f"(d[2]), "+f"(d[3])
        : "r"(a[0]), "r"(a[1]), "r"(a[2]), "r"(a[3]), "r"(b0), "r"(b1));
}

// Inline BN-affine coefficients from a stats slot (threads t<128 write smem).
// CTYPE 1: relu(bn1(y + fc1_b)) -> a = g*rsqrt(var), s = b - mu*a   (fc bias cancels)
// CTYPE 2: relu(bn3(bn2(y + fc2_b))) -> composed analytically (b2, bn2_b cancel)
template <int CTYPE>
__device__ __forceinline__ void coef_from_slot(int t, int slot,
                                               const float* __restrict__ p0,
                                               const float* __restrict__ p1,
                                               const float* __restrict__ p2,
                                               float* ta_s, float* ts_s) {
    if (t < 128) {
        float mu = g_accs[slot * H + t] * (1.f / NNODE);
        float var = g_accq[slot * H + t] * (1.f / NNODE) - mu * mu;
        if (CTYPE == 1) {
            float a = p0[t] * rsqrtf(var + BN_EPS);
            ta_s[t] = a;
            ts_s[t] = p1[t] - mu * a;
        } else {
            float r2 = rsqrtf(var + BN_EPS);
            float gr = p0[t] * r2;
            float v3 = gr * gr * var;
            float A = gr * p1[t] * rsqrtf(v3 + BN_EPS);
            ta_s[t] = A;
            ts_s[t] = p2[t] - mu * A;
        }
    }
}

// ---------------- CSR build ---------------------------------------------------
__global__ void zero_k() {
    int i = blockIdx.x * blockDim.x + threadIdx.x;
    if (i < NNODE) g_counts[i] = 0;
    if (i < 8 * H) { g_accs[i] = 0.f; g_accq[i] = 0.f; }
}

__global__ void hist_k(const int* __restrict__ dst) {
    int e = blockIdx.x * blockDim.x + threadIdx.x;
    if (e < NEDGE) atomicAdd(&g_counts[dst[e]], 1);
}

// 1024-thread single-block scan, int4 per thread per iteration (13 iterations).
__global__ void scan_k() {
    __shared__ int wsum[32];
    __shared__ int carry_s;
    int t = threadIdx.x;
    int lane = t & 31;
    if (t == 0) carry_s = 0;
    __syncthreads();
    #pragma unroll 1
    for (int it = 0; it < NPADC / 4096; ++it) {
        int i4 = it * 4096 + t * 4;
        int4 c = *(const int4*)(g_counts + i4);   // pad region is always 0
        int s0 = c.x, s1 = s0 + c.y, s2 = s1 + c.z, s3 = s2 + c.w;
        int x = s3;
        #pragma unroll
        for (int d = 1; d < 32; d <<= 1) {
            int y = __shfl_up_sync(0xffffffffu, x, d);
            if (lane >= d) x += y;
        }
        if (lane == 31) wsum[t >> 5] = x;
        __syncthreads();
        if (t < 32) {
            int y = wsum[t];
            #pragma unroll
            for (int d = 1; d < 32; d <<= 1) {
                int z = __shfl_up_sync(0xffffffffu, y, d);
                if (t >= d) y += z;
            }
            wsum[t] = y;
        }
        __syncthreads();
        int base = carry_s + ((t >= 32) ? wsum[(t >> 5) - 1] : 0) + x - s3;
        if (i4 + 0 < NNODE) { g_offs[i4 + 0] = base;      g_cursor[i4 + 0] = base; }
        if (i4 + 1 < NNODE) { g_offs[i4 + 1] = base + s0; g_cursor[i4 + 1] = base + s0; }
        if (i4 + 2 < NNODE) { g_offs[i4 + 2] = base + s1; g_cursor[i4 + 2] = base + s1; }
        if (i4 + 3 < NNODE) { g_offs[i4 + 3] = base + s2; g_cursor[i4 + 3] = base + s2; }
        int tot = wsum[31];
        __syncthreads();
        if (t == 0) carry_s += tot;
        __syncthreads();
    }
    if (t == 0) g_offs[NNODE] = NEDGE;
}

__global__ void fill_k(const int* __restrict__ ei) {
    int e = blockIdx.x * blockDim.x + threadIdx.x;
    if (e < NEDGE) {
        int d = ei[NEDGE + e];          // dst row of edge_index [2, E]
        int pos = atomicAdd(&g_cursor[d], 1);
        g_ssrc[pos] = ei[e];            // src
    }
}

// ---------------- aggregation: g_h = T(x_v) + sum_{j in N(v)} T(x_j) ----------
// T = identity (layer 0) or composed bn2/bn3 affine+relu computed inline from
// the previous gemm2's stats slot (CTYPE 2).  High occupancy: 8 nodes/block.
template <bool TRANS>
__global__ __launch_bounds__(256) void agg_k(const float* __restrict__ xext,
                                             int slot_in,
                                             const float* __restrict__ p0,
                                             const float* __restrict__ p1,
                                             const float* __restrict__ p2) {
    __shared__ float ta_s[128], ts_s[128];
    const float* in = TRANS ? (const float*)g_t2 : xext;
    int t = threadIdx.x;

    if (TRANS) {
        coef_from_slot<2>(t, slot_in, p0, p1, p2, ta_s, ts_s);
        __syncthreads();
    }

    int lane = t & 31;
    int node = blockIdx.x * 8 + (t >> 5);
    if (node >= HPAD) return;
    int cb = lane * 4;
    float4* outp = (float4*)(g_h + (size_t)node * H + cb);
    if (node >= NNODE) { *outp = f4zero(); return; }

    float4 Aa = f4zero(), Ss = f4zero();
    if (TRANS) {
        Aa = *(const float4*)(ta_s + cb);
        Ss = *(const float4*)(ts_s + cb);
    }

    float4 a0, a1 = f4zero(), a2 = f4zero(), a3 = f4zero();
    {
        float4 v = *(const float4*)(in + (size_t)node * H + cb);
        a0 = TRANS ? f4affine_relu(v, Aa, Ss) : v;
    }
    int j = g_offs[node];
    int jend = g_offs[node + 1];
    for (; j + 3 < jend; j += 4) {
        int s0 = g_ssrc[j], s1 = g_ssrc[j + 1], s2 = g_ssrc[j + 2], s3 = g_ssrc[j + 3];
        float4 v0 = *(const float4*)(in + (size_t)s0 * H + cb);
        float4 v1 = *(const float4*)(in + (size_t)s1 * H + cb);
        float4 v2 = *(const float4*)(in + (size_t)s2 * H + cb);
        float4 v3 = *(const float4*)(in + (size_t)s3 * H + cb);
        if (TRANS) {
            v0 = f4affine_relu(v0, Aa, Ss); v1 = f4affine_relu(v1, Aa, Ss);
            v2 = f4affine_relu(v2, Aa, Ss); v3 = f4affine_relu(v3, Aa, Ss);
        }
        f4add(a0, v0); f4add(a1, v1); f4add(a2, v2); f4add(a3, v3);
    }
    for (; j < jend; ++j) {
        float4 v = *(const float4*)(in + (size_t)g_ssrc[j] * H + cb);
        if (TRANS) v = f4affine_relu(v, Aa, Ss);
        f4add(a0, v);
    }
    f4add(a0, a1); f4add(a2, a3); f4add(a0, a2);
    *outp = a0;
}

// ---------------- tensor-core GEMM (bf16x3 split, m16n8k16) -------------------
// out[n,o] = sum_k T(A[n,k]) * W[o,k]
// CTYPE 0: T = identity (A = g_h, already transformed by agg_k)
// CTYPE 1: T = relu(bn1-affine) from slot_in    (A = g_t1)
// CTYPE 2: T = relu(bn3∘bn2-affine) from slot_in (A = g_t2, final classifier)
#define SMP 136   // word pitch: conflict-free LDS.64 / STS.128 patterns
#define GEMM_SMEM_BYTES (2 * 128 * SMP * 4 + 256 * 4)

template <int CTYPE, bool STATS, bool BIAS>
__global__ __launch_bounds__(256, 1) void gemm_tc(
    int asel, const float* __restrict__ W, float* __restrict__ oext,
    int slot_in, int slot_out,
    const float* __restrict__ p0, const float* __restrict__ p1,
    const float* __restrict__ p2,
    const float* __restrict__ bias, int storeN) {
    const float* A = (asel == 0) ? g_h : (asel == 1) ? g_t1 : g_t2;
    float* out;
    if (BIAS) out = oext;
    else      out = (asel == 0) ? g_t1 : g_t2;

    extern __shared__ uint32_t sm[];
    uint32_t* As = sm;                    // [128][SMP] packed hi|lo
    uint32_t* Ws = sm + 128 * SMP;        // [128][SMP]
    float* ta_s = (float*)(sm + 2 * 128 * SMP);
    float* ts_s = ta_s + 128;

    int t = threadIdx.x;
    int m0 = blockIdx.x * 128;

    if (CTYPE != 0) {
        coef_from_slot<CTYPE>(t, slot_in, p0, p1, p2, ta_s, ts_s);
        __syncthreads();
    }

    // ---- fill smem: A (optional affine+relu, row guard) and W, split-packed --
    #pragma unroll
    for (int j = 0; j < 16; ++j) {
        int idx = t + j * 256;
        int row = idx >> 5;          // 0..127
        int q = idx & 31;            // float4 index along K
        int gr = m0 + row;
        float4 v = f4zero();
        if (gr < NNODE) {
            v = *(const float4*)(A + (size_t)gr * H + q * 4);
            if (CTYPE != 0) {
                float4 a4 = *(const float4*)(ta_s + q * 4);
                float4 s4 = *(const float4*)(ts_s + q * 4);
                v = f4affine_relu(v, a4, s4);
            }
        }
        *(uint4*)(As + row * SMP + q * 4) = pack_split4(v);

        float4 wv = *(const float4*)(W + (size_t)row * H + q * 4);
        *(uint4*)(Ws + row * SMP + q * 4) = pack_split4(wv);
    }
    __syncthreads();

    int lane = t & 31;
    int w = t >> 5;
    int wm = w & 3;          // m-warp 0..3  (rows wm*32)
    int wn = w >> 2;         // n-warp 0..1  (cols wn*64)
    int g = lane >> 2;
    int tig = lane & 3;
    int mb = wm * 32;
    int nb = wn * 64;

    float d[2][8][4];
    #pragma unroll
    for (int mt = 0; mt < 2; ++mt)
        #pragma unroll
        for (int nt = 0; nt < 8; ++nt)
            #pragma unroll
            for (int i = 0; i < 4; ++i) d[mt][nt][i] = 0.f;

    #pragma unroll
    for (int ks = 0; ks < 8; ++ks) {
        int k0 = ks * 16;
        uint32_t ah[2][4], al[2][4];
        #pragma unroll
        for (int mt = 0; mt < 2; ++mt) {
            int r0 = mb + mt * 16 + g;
            uint2 w0 = *(const uint2*)(As + r0 * SMP + k0 + 2 * tig);
            uint2 w1 = *(const uint2*)(As + (r0 + 8) * SMP + k0 + 2 * tig);
            uint2 w2 = *(const uint2*)(As + r0 * SMP + k0 + 8 + 2 * tig);
            uint2 w3 = *(const uint2*)(As + (r0 + 8) * SMP + k0 + 8 + 2 * tig);
            ah[mt][0] = __byte_perm(w0.x, w0.y, 0x5410); al[mt][0] = __byte_perm(w0.x, w0.y, 0x7632);
            ah[mt][1] = __byte_perm(w1.x, w1.y, 0x5410); al[mt][1] = __byte_perm(w1.x, w1.y, 0x7632);
            ah[mt][2] = __byte_perm(w2.x, w2.y, 0x5410); al[mt][2] = __byte_perm(w2.x, w2.y, 0x7632);
            ah[mt][3] = __byte_perm(w3.x, w3.y, 0x5410); al[mt][3] = __byte_perm(w3.x, w3.y, 0x7632);
        }
        #pragma unroll
        for (int nt = 0; nt < 8; ++nt) {
            int o = nb + nt * 8 + g;
            uint2 u0 = *(const uint2*)(Ws + o * SMP + k0 + 2 * tig);
            uint2 u1 = *(const uint2*)(Ws + o * SMP + k0 + 8 + 2 * tig);
            uint32_t bh0 = __byte_perm(u0.x, u0.y, 0x5410);
            uint32_t bl0 = __byte_perm(u0.x, u0.y, 0x7632);
            uint32_t bh1 = __byte_perm(u1.x, u1.y, 0x5410);
            uint32_t bl1 = __byte_perm(u1.x, u1.y, 0x7632);
            #pragma unroll
            for (int mt = 0; mt < 2; ++mt) {
                mma_bf16(d[mt][nt], ah[mt], bh0, bh1);   // hi*hi
                mma_bf16(d[mt][nt], al[mt], bh0, bh1);   // lo*hi
                mma_bf16(d[mt][nt], ah[mt], bl0, bl1);   // hi*lo
            }
        }
    }

    // ---- stats: per-column sum / sumsq (padded rows contribute exact zeros) --
    if (STATS) {
        float s[8][2], q[8][2];
        #pragma unroll
        for (int nt = 0; nt < 8; ++nt)
            #pragma unroll
            for (int j = 0; j < 2; ++j) {
                float sv = 0.f, qv = 0.f;
                #pragma unroll
                for (int mt = 0; mt < 2; ++mt) {
                    float v0 = d[mt][nt][j], v1 = d[mt][nt][j + 2];
                    sv += v0 + v1;
                    qv = fmaf(v0, v0, fmaf(v1, v1, qv));
                }
                #pragma unroll
                for (int off = 4; off < 32; off <<= 1) {
                    sv += __shfl_xor_sync(0xffffffffu, sv, off);
                    qv += __shfl_xor_sync(0xffffffffu, qv, off);
                }
                s[nt][j] = sv; q[nt][j] = qv;
            }
        __syncthreads();                      // done reading As/Ws; reuse as Red
        float* RedS = (float*)sm;             // [8][64]
        float* RedQ = (float*)sm + 512;       // [8][64]
        if (g == 0) {
            #pragma unroll
            for (int nt = 0; nt < 8; ++nt)
                #pragma unroll
                for (int j = 0; j < 2; ++j) {
                    int lc = nt * 8 + tig * 2 + j;
                    RedS[w * 64 + lc] = s[nt][j];
                    RedQ[w * 64 + lc] = q[nt][j];
                }
        }
        __syncthreads();
        if (t < 128) {
            int gsel = t >> 6;
            int lc = t & 63;
            float sv = 0.f, qv = 0.f;
            #pragma unroll
            for (int ww = 0; ww < 4; ++ww) {
                sv += RedS[(gsel * 4 + ww) * 64 + lc];
                qv += RedQ[(gsel * 4 + ww) * 64 + lc];
            }
            atomicAdd(&g_accs[slot_out * H + gsel * 64 + lc], sv);
            atomicAdd(&g_accq[slot_out * H + gsel * 64 + lc], qv);
        }
    }

    // ---- store C ----
    #pragma unroll
    for (int nt = 0; nt < 8; ++nt) {
        int col = nb + nt * 8 + tig * 2;
        float2 bb = make_float2(0.f, 0.f);
        if (BIAS) bb = *(const float2*)(bias + col);
        #pragma unroll
        for (int mt = 0; mt < 2; ++mt) {
            int r0 = m0 + mb + mt * 16 + g;
            if (r0 < storeN) {
                float2 v = make_float2(d[mt][nt][0] + bb.x, d[mt][nt][1] + bb.y);
                *(float2*)(out + (size_t)r0 * H + col) = v;
            }
            if (r0 + 8 < storeN) {
                float2 v = make_float2(d[mt][nt][2] + bb.x, d[mt][nt][3] + bb.y);
                *(float2*)(out + (size_t)(r0 + 8) * H + col) = v;
            }
        }
    }
}

// ---------------- launch ------------------------------------------------------
extern "C" void kernel_launch(void* const* d_in, const int* in_sizes, int n_in,
                              void* d_out, int out_size) {
    const float* x     = (const float*)d_in[0];
    const int*   ei    = (const int*)  d_in[1];
    const float* fc1_w = (const float*)d_in[2];
    const float* bn1_g = (const float*)d_in[4];
    const float* bn1_b = (const float*)d_in[5];
    const float* fc2_w = (const float*)d_in[6];
    const float* bn2_g = (const float*)d_in[8];
    const float* bn3_g = (const float*)d_in[10];
    const float* bn3_b = (const float*)d_in[11];
    const float* fc_w  = (const float*)d_in[12];
    const float* fc_b  = (const float*)d_in[13];
    float* out = (float*)d_out;

    cudaFuncSetAttribute(gemm_tc<0, true,  false>,
                         cudaFuncAttributeMaxDynamicSharedMemorySize, GEMM_SMEM_BYTES);
    cudaFuncSetAttribute(gemm_tc<1, true,  false>,
                         cudaFuncAttributeMaxDynamicSharedMemorySize, GEMM_SMEM_BYTES);
    cudaFuncSetAttribute(gemm_tc<2, false, true >,
                         cudaFuncAttributeMaxDynamicSharedMemorySize, GEMM_SMEM_BYTES);

    zero_k<<<(NNODE + 255) / 256, 256>>>();
    hist_k<<<(NEDGE + 255) / 256, 256>>>(ei + NEDGE);
    scan_k<<<1, 1024>>>();
    fill_k<<<(NEDGE + 255) / 256, 256>>>(ei);

    const int GEMM_GRID = HPAD / 128;   // 391
    const int AGG_GRID  = HPAD / 8;     // 6256

    for (int i = 0; i < LNUM; ++i) {
        if (i == 0)
            agg_k<false><<<AGG_GRID, 256>>>(x, -1, nullptr, nullptr, nullptr);
        else
            agg_k<true><<<AGG_GRID, 256>>>(nullptr, 2 * i - 1,
                                           bn2_g + (i - 1) * H, bn3_g + (i - 1) * H,
                                           bn3_b + (i - 1) * H);
        // gemm1: g_t1 = g_h @ fc1_w^T, stats -> slot 2i
        gemm_tc<0, true, false><<<GEMM_GRID, 256, GEMM_SMEM_BYTES>>>(
            0, fc1_w + (size_t)i * H * H, nullptr, -1, 2 * i,
            nullptr, nullptr, nullptr, nullptr, HPAD);
        // gemm2: g_t2 = relu(bn1-affine(g_t1)) @ fc2_w^T, stats -> slot 2i+1
        gemm_tc<1, true, false><<<GEMM_GRID, 256, GEMM_SMEM_BYTES>>>(
            1, fc2_w + (size_t)i * H * H, nullptr, 2 * i, 2 * i + 1,
            bn1_g + i * H, bn1_b + i * H, nullptr, nullptr, HPAD);
    }
    // final classifier: out = relu(bn3∘bn2-affine(g_t2)) @ fc_w^T + fc_b
    gemm_tc<2, false, true><<<GEMM_GRID, 256, GEMM_SMEM_BYTES>>>(
        2, fc_w, out, 7, -1,
        bn2_g + 3 * H, bn3_g + 3 * H, bn3_b + 3 * H, fc_b, NNODE);
}

// round 6
// speedup vs baseline: 1.3646x; 1.0735x over previous
#include <cuda_runtime.h>
#include <cuda_bf16.h>
#include <cstdint>

#define NNODE 50000
#define NEDGE 800000
#define H 128
#define LNUM 4
#define HPAD 50048            // 391 * 128 = 782 * 64
#define NPADC 53248           // 13 * 4096, padded counts for int4 scan
#define BN_EPS 1e-5f

#define SMP 136               // smem word pitch (8 mod 32 -> conflict-free LDS.64)
#define WWORDS (128 * SMP)    // packed weight matrix footprint (incl. pitch pad)

// ---------------- device scratch (allocation-free rule: __device__ globals) ---
__device__ int      g_counts[NPADC];   // pad tail beyond NNODE stays 0 forever
__device__ int      g_cursor[NNODE];
__device__ int      g_offs[NNODE + 1];
__device__ int      g_ssrc[NEDGE];
__device__ float    g_h [(size_t)HPAD * H];
__device__ float    g_t1[(size_t)HPAD * H];
__device__ float    g_t2[(size_t)HPAD * H];
__device__ float    g_accs[8 * H];     // per-producer-GEMM stats slots
__device__ float    g_accq[8 * H];
__device__ uint32_t g_wp[9 * WWORDS];  // pre-split-packed weights, smem layout

// ---------------- helpers ----------------------------------------------------
__device__ __forceinline__ float4 f4zero() { return make_float4(0.f, 0.f, 0.f, 0.f); }
__device__ __forceinline__ void f4add(float4& a, const float4 b) {
    a.x += b.x; a.y += b.y; a.z += b.z; a.w += b.w;
}
__device__ __forceinline__ float4 f4affine_relu(float4 v, float4 a, float4 s) {
    float4 r;
    r.x = fmaxf(fmaf(a.x, v.x, s.x), 0.f);
    r.y = fmaxf(fmaf(a.y, v.y, s.y), 0.f);
    r.z = fmaxf(fmaf(a.z, v.z, s.z), 0.f);
    r.w = fmaxf(fmaf(a.w, v.w, s.w), 0.f);
    return r;
}
// split fp32 -> (bf16 hi | bf16 lo) packed in one 32-bit word (lo in high half)
__device__ __forceinline__ uint32_t pack_split(float v) {
    __nv_bfloat16 h = __float2bfloat16(v);
    float hf = __bfloat162float(h);
    __nv_bfloat16 l = __float2bfloat16(v - hf);
    return (uint32_t)__bfloat16_as_ushort(h) | ((uint32_t)__bfloat16_as_ushort(l) << 16);
}
__device__ __forceinline__ uint4 pack_split4(float4 v) {
    return make_uint4(pack_split(v.x), pack_split(v.y), pack_split(v.z), pack_split(v.w));
}
__device__ __forceinline__ void mma_bf16(float d[4], const uint32_t a[4],
                                         uint32_t b0, uint32_t b1) {
    asm volatile(
        "mma.sync.aligned.m16n8k16.row.col.f32.bf16.bf16.f32 "
        "{%0,%1,%2,%3}, {%4,%5,%6,%7}, {%8,%9}, {%0,%1,%2,%3};\n"
        : "+f"(d[0]), "+f"(d[1]), "+f"(d[2]), "+f"(d[3])
        : "r"(a[0]), "r"(a[1]), "r"(a[2]), "r"(a[3]), "r"(b0), "r"(b1));
}

// Inline BN-affine coefficients from a stats slot (threads t<128 write smem).
// CTYPE 1: relu(bn1(y + fc1_b)) -> a = g*rsqrt(var), s = b - mu*a   (fc bias cancels)
// CTYPE 2: relu(bn3(bn2(y + fc2_b))) -> composed analytically (b2, bn2_b cancel)
template <int CTYPE>
__device__ __forceinline__ void coef_from_slot(int t, int slot,
                                               const float* __restrict__ p0,
                                               const float* __restrict__ p1,
                                               const float* __restrict__ p2,
                                               float* ta_s, float* ts_s) {
    if (t < 128) {
        float mu = g_accs[slot * H + t] * (1.f / NNODE);
        float var = g_accq[slot * H + t] * (1.f / NNODE) - mu * mu;
        if (CTYPE == 1) {
            float a = p0[t] * rsqrtf(var + BN_EPS);
            ta_s[t] = a;
            ts_s[t] = p1[t] - mu * a;
        } else {
            float r2 = rsqrtf(var + BN_EPS);
            float gr = p0[t] * r2;
            float v3 = gr * gr * var;
            float A = gr * p1[t] * rsqrtf(v3 + BN_EPS);
            ta_s[t] = A;
            ts_s[t] = p2[t] - mu * A;
        }
    }
}

// ---------------- weight pre-packing ------------------------------------------
// Matrices 0-3: fc1_w per layer; 4-7: fc2_w per layer; 8: fc_w.
// Stored with the smem pitch so GEMM W-fill is a raw uint4 copy.
__global__ void packw_k(const float* __restrict__ fc1_w,
                        const float* __restrict__ fc2_w,
                        const float* __restrict__ fc_w) {
    int idx = blockIdx.x * blockDim.x + threadIdx.x;
    if (idx >= 9 * WWORDS) return;
    int m = idx / WWORDS;
    int rem = idx - m * WWORDS;
    int r = rem / SMP, c = rem - r * SMP;
    uint32_t v = 0;
    if (c < 128) {
        const float* src = (m < 4) ? fc1_w + (size_t)m * (H * H)
                         : (m < 8) ? fc2_w + (size_t)(m - 4) * (H * H)
                         : fc_w;
        v = pack_split(src[r * H + c]);
    }
    g_wp[idx] = v;
}

// ---------------- CSR build ---------------------------------------------------
__global__ void zero_k() {
    int i = blockIdx.x * blockDim.x + threadIdx.x;
    if (i < NNODE) g_counts[i] = 0;
    if (i < 8 * H) { g_accs[i] = 0.f; g_accq[i] = 0.f; }
}

__global__ void hist_k(const int* __restrict__ dst) {
    int e = blockIdx.x * blockDim.x + threadIdx.x;
    if (e < NEDGE) atomicAdd(&g_counts[dst[e]], 1);
}

// 1024-thread single-block scan, int4 per thread per iteration (13 iterations).
__global__ void scan_k() {
    __shared__ int wsum[32];
    __shared__ int carry_s;
    int t = threadIdx.x;
    int lane = t & 31;
    if (t == 0) carry_s = 0;
    __syncthreads();
    #pragma unroll 1
    for (int it = 0; it < NPADC / 4096; ++it) {
        int i4 = it * 4096 + t * 4;
        int4 c = *(const int4*)(g_counts + i4);   // pad region is always 0
        int s0 = c.x, s1 = s0 + c.y, s2 = s1 + c.z, s3 = s2 + c.w;
        int x = s3;
        #pragma unroll
        for (int d = 1; d < 32; d <<= 1) {
            int y = __shfl_up_sync(0xffffffffu, x, d);
            if (lane >= d) x += y;
        }
        if (lane == 31) wsum[t >> 5] = x;
        __syncthreads();
        if (t < 32) {
            int y = wsum[t];
            #pragma unroll
            for (int d = 1; d < 32; d <<= 1) {
                int z = __shfl_up_sync(0xffffffffu, y, d);
                if (t >= d) y += z;
            }
            wsum[t] = y;
        }
        __syncthreads();
        int base = carry_s + ((t >= 32) ? wsum[(t >> 5) - 1] : 0) + x - s3;
        if (i4 + 0 < NNODE) { g_offs[i4 + 0] = base;      g_cursor[i4 + 0] = base; }
        if (i4 + 1 < NNODE) { g_offs[i4 + 1] = base + s0; g_cursor[i4 + 1] = base + s0; }
        if (i4 + 2 < NNODE) { g_offs[i4 + 2] = base + s1; g_cursor[i4 + 2] = base + s1; }
        if (i4 + 3 < NNODE) { g_offs[i4 + 3] = base + s2; g_cursor[i4 + 3] = base + s2; }
        int tot = wsum[31];
        __syncthreads();
        if (t == 0) carry_s += tot;
        __syncthreads();
    }
    if (t == 0) g_offs[NNODE] = NEDGE;
}

__global__ void fill_k(const int* __restrict__ ei) {
    int e = blockIdx.x * blockDim.x + threadIdx.x;
    if (e < NEDGE) {
        int d = ei[NEDGE + e];          // dst row of edge_index [2, E]
        int pos = atomicAdd(&g_cursor[d], 1);
        g_ssrc[pos] = ei[e];            // src
    }
}

// ---------------- aggregation: g_h = T(x_v) + sum_{j in N(v)} T(x_j) ----------
// T = identity (layer 0) or composed bn2/bn3 affine+relu computed inline from
// the previous gemm2's stats slot (CTYPE 2).  High occupancy: 8 nodes/block.
template <bool TRANS>
__global__ __launch_bounds__(256) void agg_k(const float* __restrict__ xext,
                                             int slot_in,
                                             const float* __restrict__ p0,
                                             const float* __restrict__ p1,
                                             const float* __restrict__ p2) {
    __shared__ float ta_s[128], ts_s[128];
    const float* in = TRANS ? (const float*)g_t2 : xext;
    int t = threadIdx.x;

    if (TRANS) {
        coef_from_slot<2>(t, slot_in, p0, p1, p2, ta_s, ts_s);
        __syncthreads();
    }

    int lane = t & 31;
    int node = blockIdx.x * 8 + (t >> 5);
    if (node >= HPAD) return;
    int cb = lane * 4;
    float4* outp = (float4*)(g_h + (size_t)node * H + cb);
    if (node >= NNODE) { *outp = f4zero(); return; }

    float4 Aa = f4zero(), Ss = f4zero();
    if (TRANS) {
        Aa = *(const float4*)(ta_s + cb);
        Ss = *(const float4*)(ts_s + cb);
    }

    float4 a0, a1 = f4zero(), a2 = f4zero(), a3 = f4zero();
    {
        float4 v = *(const float4*)(in + (size_t)node * H + cb);
        a0 = TRANS ? f4affine_relu(v, Aa, Ss) : v;
    }
    int j = g_offs[node];
    int jend = g_offs[node + 1];
    for (; j + 3 < jend; j += 4) {
        int s0 = g_ssrc[j], s1 = g_ssrc[j + 1], s2 = g_ssrc[j + 2], s3 = g_ssrc[j + 3];
        float4 v0 = *(const float4*)(in + (size_t)s0 * H + cb);
        float4 v1 = *(const float4*)(in + (size_t)s1 * H + cb);
        float4 v2 = *(const float4*)(in + (size_t)s2 * H + cb);
        float4 v3 = *(const float4*)(in + (size_t)s3 * H + cb);
        if (TRANS) {
            v0 = f4affine_relu(v0, Aa, Ss); v1 = f4affine_relu(v1, Aa, Ss);
            v2 = f4affine_relu(v2, Aa, Ss); v3 = f4affine_relu(v3, Aa, Ss);
        }
        f4add(a0, v0); f4add(a1, v1); f4add(a2, v2); f4add(a3, v3);
    }
    for (; j < jend; ++j) {
        float4 v = *(const float4*)(in + (size_t)g_ssrc[j] * H + cb);
        if (TRANS) v = f4affine_relu(v, Aa, Ss);
        f4add(a0, v);
    }
    f4add(a0, a1); f4add(a2, a3); f4add(a0, a2);
    *outp = a0;
}

// ---------------- tensor-core GEMM (bf16x3 split, m16n8k16) -------------------
// out[n,o] = sum_k T(A[n,k]) * W[o,k]   BM=64, 2 CTAs/SM.
// CTYPE 0: T = identity (A = g_h, already transformed by agg_k)
// CTYPE 1: T = relu(bn1-affine) from slot_in     (A = g_t1)
// CTYPE 2: T = relu(bn3∘bn2-affine) from slot_in (A = g_t2, final classifier)
// 8 warps = 2(m) x 4(n); warp tile m32 x n32.
#define ASZ (64 * SMP)
#define GEMM_SMEM_BYTES ((ASZ + WWORDS + 256) * 4)

template <int CTYPE, bool STATS, bool BIAS>
__global__ __launch_bounds__(256, 2) void gemm_tc(
    int asel, int wsel, float* __restrict__ oext,
    int slot_in, int slot_out,
    const float* __restrict__ p0, const float* __restrict__ p1,
    const float* __restrict__ p2,
    const float* __restrict__ bias, int storeN) {
    const float* A = (asel == 0) ? g_h : (asel == 1) ? g_t1 : g_t2;
    float* out;
    if (BIAS) out = oext;
    else      out = (asel == 0) ? g_t1 : g_t2;

    extern __shared__ uint32_t sm[];
    uint32_t* As = sm;                    // [64][SMP] packed hi|lo
    uint32_t* Ws = sm + ASZ;              // [128][SMP]
    float* ta_s = (float*)(sm + ASZ + WWORDS);
    float* ts_s = ta_s + 128;

    int t = threadIdx.x;
    int m0 = blockIdx.x * 64;

    if (CTYPE != 0) {
        coef_from_slot<CTYPE>(t, slot_in, p0, p1, p2, ta_s, ts_s);
        __syncthreads();
    }

    // ---- W fill: raw copy of pre-packed weights (17 x uint4 per thread) ----
    {
        const uint4* wsrc = (const uint4*)(g_wp + (size_t)wsel * WWORDS);
        uint4* wdst = (uint4*)Ws;
        #pragma unroll
        for (int j = 0; j < 17; ++j) wdst[t + j * 256] = wsrc[t + j * 256];
    }

    // ---- A fill: 8 float4 per thread, optional affine+relu, split-pack ----
    #pragma unroll
    for (int j = 0; j < 8; ++j) {
        int idx = t + j * 256;
        int row = idx >> 5;          // 0..63
        int q = idx & 31;            // float4 index along K
        int gr = m0 + row;
        float4 v = f4zero();
        if (gr < NNODE) {
            v = *(const float4*)(A + (size_t)gr * H + q * 4);
            if (CTYPE != 0) {
                float4 a4 = *(const float4*)(ta_s + q * 4);
                float4 s4 = *(const float4*)(ts_s + q * 4);
                v = f4affine_relu(v, a4, s4);
            }
        }
        *(uint4*)(As + row * SMP + q * 4) = pack_split4(v);
    }
    __syncthreads();

    int lane = t & 31;
    int w = t >> 5;
    int wm = w >> 2;         // m-warp 0..1  (rows wm*32)
    int wn = w & 3;          // n-warp 0..3  (cols wn*32)
    int g = lane >> 2;
    int tig = lane & 3;
    int mb = wm * 32;
    int nb = wn * 32;

    float d[2][4][4];
    #pragma unroll
    for (int mt = 0; mt < 2; ++mt)
        #pragma unroll
        for (int nt = 0; nt < 4; ++nt)
            #pragma unroll
            for (int i = 0; i < 4; ++i) d[mt][nt][i] = 0.f;

    #pragma unroll
    for (int ks = 0; ks < 8; ++ks) {
        int k0 = ks * 16;
        uint32_t ah[2][4], al[2][4];
        #pragma unroll
        for (int mt = 0; mt < 2; ++mt) {
            int r0 = mb + mt * 16 + g;
            uint2 w0 = *(const uint2*)(As + r0 * SMP + k0 + 2 * tig);
            uint2 w1 = *(const uint2*)(As + (r0 + 8) * SMP + k0 + 2 * tig);
            uint2 w2 = *(const uint2*)(As + r0 * SMP + k0 + 8 + 2 * tig);
            uint2 w3 = *(const uint2*)(As + (r0 + 8) * SMP + k0 + 8 + 2 * tig);
            ah[mt][0] = __byte_perm(w0.x, w0.y, 0x5410); al[mt][0] = __byte_perm(w0.x, w0.y, 0x7632);
            ah[mt][1] = __byte_perm(w1.x, w1.y, 0x5410); al[mt][1] = __byte_perm(w1.x, w1.y, 0x7632);
            ah[mt][2] = __byte_perm(w2.x, w2.y, 0x5410); al[mt][2] = __byte_perm(w2.x, w2.y, 0x7632);
            ah[mt][3] = __byte_perm(w3.x, w3.y, 0x5410); al[mt][3] = __byte_perm(w3.x, w3.y, 0x7632);
        }
        #pragma unroll
        for (int nt = 0; nt < 4; ++nt) {
            int o = nb + nt * 8 + g;
            uint2 u0 = *(const uint2*)(Ws + o * SMP + k0 + 2 * tig);
            uint2 u1 = *(const uint2*)(Ws + o * SMP + k0 + 8 + 2 * tig);
            uint32_t bh0 = __byte_perm(u0.x, u0.y, 0x5410);
            uint32_t bl0 = __byte_perm(u0.x, u0.y, 0x7632);
            uint32_t bh1 = __byte_perm(u1.x, u1.y, 0x5410);
            uint32_t bl1 = __byte_perm(u1.x, u1.y, 0x7632);
            #pragma unroll
            for (int mt = 0; mt < 2; ++mt) {
                mma_bf16(d[mt][nt], ah[mt], bh0, bh1);   // hi*hi
                mma_bf16(d[mt][nt], al[mt], bh0, bh1);   // lo*hi
                mma_bf16(d[mt][nt], ah[mt], bl0, bl1);   // hi*lo
            }
        }
    }

    // ---- stats: per-column sum / sumsq (padded rows contribute exact zeros) --
    if (STATS) {
        float s[4][2], q[4][2];
        #pragma unroll
        for (int nt = 0; nt < 4; ++nt)
            #pragma unroll
            for (int j = 0; j < 2; ++j) {
                float sv = 0.f, qv = 0.f;
                #pragma unroll
                for (int mt = 0; mt < 2; ++mt) {
                    float v0 = d[mt][nt][j], v1 = d[mt][nt][j + 2];
                    sv += v0 + v1;
                    qv = fmaf(v0, v0, fmaf(v1, v1, qv));
                }
                #pragma unroll
                for (int off = 4; off < 32; off <<= 1) {
                    sv += __shfl_xor_sync(0xffffffffu, sv, off);
                    qv += __shfl_xor_sync(0xffffffffu, qv, off);
                }
                s[nt][j] = sv; q[nt][j] = qv;
            }
        __syncthreads();                      // done reading As/Ws; reuse as Red
        float* RedS = (float*)sm;             // [8][32]
        float* RedQ = (float*)sm + 256;       // [8][32]
        if (g == 0) {
            #pragma unroll
            for (int nt = 0; nt < 4; ++nt)
                #pragma unroll
                for (int j = 0; j < 2; ++j) {
                    int lc = nt * 8 + tig * 2 + j;
                    RedS[w * 32 + lc] = s[nt][j];
                    RedQ[w * 32 + lc] = q[nt][j];
                }
        }
        __syncthreads();
        if (t < 128) {
            int wn2 = t >> 5;
            int lc = t & 31;
            float sv = RedS[wn2 * 32 + lc] + RedS[(wn2 + 4) * 32 + lc];
            float qv = RedQ[wn2 * 32 + lc] + RedQ[(wn2 + 4) * 32 + lc];
            atomicAdd(&g_accs[slot_out * H + t], sv);
            atomicAdd(&g_accq[slot_out * H + t], qv);
        }
    }

    // ---- store C ----
    #pragma unroll
    for (int nt = 0; nt < 4; ++nt) {
        int col = nb + nt * 8 + tig * 2;
        float2 bb = make_float2(0.f, 0.f);
        if (BIAS) bb = *(const float2*)(bias + col);
        #pragma unroll
        for (int mt = 0; mt < 2; ++mt) {
            int r0 = m0 + mb + mt * 16 + g;
            if (r0 < storeN) {
                float2 v = make_float2(d[mt][nt][0] + bb.x, d[mt][nt][1] + bb.y);
                *(float2*)(out + (size_t)r0 * H + col) = v;
            }
            if (r0 + 8 < storeN) {
                float2 v = make_float2(d[mt][nt][2] + bb.x, d[mt][nt][3] + bb.y);
                *(float2*)(out + (size_t)(r0 + 8) * H + col) = v;
            }
        }
    }
}

// ---------------- launch ------------------------------------------------------
extern "C" void kernel_launch(void* const* d_in, const int* in_sizes, int n_in,
                              void* d_out, int out_size) {
    const float* x     = (const float*)d_in[0];
    const int*   ei    = (const int*)  d_in[1];
    const float* fc1_w = (const float*)d_in[2];
    const float* bn1_g = (const float*)d_in[4];
    const float* bn1_b = (const float*)d_in[5];
    const float* fc2_w = (const float*)d_in[6];
    const float* bn2_g = (const float*)d_in[8];
    const float* bn3_g = (const float*)d_in[10];
    const float* bn3_b = (const float*)d_in[11];
    const float* fc_w  = (const float*)d_in[12];
    const float* fc_b  = (const float*)d_in[13];
    float* out = (float*)d_out;

    cudaFuncSetAttribute(gemm_tc<0, true,  false>,
                         cudaFuncAttributeMaxDynamicSharedMemorySize, GEMM_SMEM_BYTES);
    cudaFuncSetAttribute(gemm_tc<1, true,  false>,
                         cudaFuncAttributeMaxDynamicSharedMemorySize, GEMM_SMEM_BYTES);
    cudaFuncSetAttribute(gemm_tc<2, false, true >,
                         cudaFuncAttributeMaxDynamicSharedMemorySize, GEMM_SMEM_BYTES);

    zero_k<<<(NNODE + 255) / 256, 256>>>();
    packw_k<<<(9 * WWORDS + 255) / 256, 256>>>(fc1_w, fc2_w, fc_w);
    hist_k<<<(NEDGE + 255) / 256, 256>>>(ei + NEDGE);
    scan_k<<<1, 1024>>>();
    fill_k<<<(NEDGE + 255) / 256, 256>>>(ei);

    const int GEMM_GRID = HPAD / 64;    // 782
    const int AGG_GRID  = HPAD / 8;     // 6256

    for (int i = 0; i < LNUM; ++i) {
        if (i == 0)
            agg_k<false><<<AGG_GRID, 256>>>(x, -1, nullptr, nullptr, nullptr);
        else
            agg_k<true><<<AGG_GRID, 256>>>(nullptr, 2 * i - 1,
                                           bn2_g + (i - 1) * H, bn3_g + (i - 1) * H,
                                           bn3_b + (i - 1) * H);
        // gemm1: g_t1 = g_h @ fc1_w[i]^T, stats -> slot 2i
        gemm_tc<0, true, false><<<GEMM_GRID, 256, GEMM_SMEM_BYTES>>>(
            0, i, nullptr, -1, 2 * i,
            nullptr, nullptr, nullptr, nullptr, HPAD);
        // gemm2: g_t2 = relu(bn1-affine(g_t1)) @ fc2_w[i]^T, stats -> slot 2i+1
        gemm_tc<1, true, false><<<GEMM_GRID, 256, GEMM_SMEM_BYTES>>>(
            1, 4 + i, nullptr, 2 * i, 2 * i + 1,
            bn1_g + i * H, bn1_b + i * H, nullptr, nullptr, HPAD);
    }
    // final classifier: out = relu(bn3∘bn2-affine(g_t2)) @ fc_w^T + fc_b
    gemm_tc<2, false, true><<<GEMM_GRID, 256, GEMM_SMEM_BYTES>>>(
        2, 8, out, 7, -1,
        bn2_g + 3 * H, bn3_g + 3 * H, bn3_b + 3 * H, fc_b, NNODE);
}

// round 7
// speedup vs baseline: 1.4867x; 1.0895x over previous
#include <cuda_runtime.h>
#include <cuda_bf16.h>
#include <cstdint>

#define NNODE 50000
#define NEDGE 800000
#define H 128
#define LNUM 4
#define HPAD 50048            // 391 * 128 = 782 * 64
#define NPADC 53248           // 52 * 1024, padded counts for int4 scan
#define BN_EPS 1e-5f

#define SMP 136               // smem word pitch (8 mod 32 -> conflict-free LDS.64)
#define WWORDS (128 * SMP)    // packed weight matrix footprint (incl. pitch pad)

#define SCAN_NBLK (NPADC / 1024)   // 52

// ---------------- device scratch (allocation-free rule: __device__ globals) ---
__device__ int      g_counts[NPADC];   // pad tail beyond NNODE stays 0 forever
__device__ int      g_cursor[NNODE];
__device__ int      g_offs[NNODE + 1];
__device__ int      g_ssrc[NEDGE];
__device__ int      g_btot[SCAN_NBLK];
__device__ int      g_bbase[SCAN_NBLK];
__device__ float    g_h [(size_t)HPAD * H];
__device__ float    g_t1[(size_t)HPAD * H];
__device__ float    g_t2[(size_t)HPAD * H];
__device__ float    g_accs[8 * H];     // per-producer-GEMM stats slots
__device__ float    g_accq[8 * H];
__device__ uint32_t g_wp[9 * WWORDS];  // pre-split-packed weights, smem layout

// ---------------- helpers ----------------------------------------------------
__device__ __forceinline__ float4 f4zero() { return make_float4(0.f, 0.f, 0.f, 0.f); }
__device__ __forceinline__ void f4add(float4& a, const float4 b) {
    a.x += b.x; a.y += b.y; a.z += b.z; a.w += b.w;
}
__device__ __forceinline__ float4 f4affine_relu(float4 v, float4 a, float4 s) {
    float4 r;
    r.x = fmaxf(fmaf(a.x, v.x, s.x), 0.f);
    r.y = fmaxf(fmaf(a.y, v.y, s.y), 0.f);
    r.z = fmaxf(fmaf(a.z, v.z, s.z), 0.f);
    r.w = fmaxf(fmaf(a.w, v.w, s.w), 0.f);
    return r;
}
// split fp32 -> (bf16 hi | bf16 lo) packed in one 32-bit word (lo in high half)
__device__ __forceinline__ uint32_t pack_split(float v) {
    __nv_bfloat16 h = __float2bfloat16(v);
    float hf = __bfloat162float(h);
    __nv_bfloat16 l = __float2bfloat16(v - hf);
    return (uint32_t)__bfloat16_as_ushort(h) | ((uint32_t)__bfloat16_as_ushort(l) << 16);
}
__device__ __forceinline__ uint4 pack_split4(float4 v) {
    return make_uint4(pack_split(v.x), pack_split(v.y), pack_split(v.z), pack_split(v.w));
}
__device__ __forceinline__ void mma_bf16(float d[4], const uint32_t a[4],
                                         uint32_t b0, uint32_t b1) {
    asm volatile(
        "mma.sync.aligned.m16n8k16.row.col.f32.bf16.bf16.f32 "
        "{%0,%1,%2,%3}, {%4,%5,%6,%7}, {%8,%9}, {%0,%1,%2,%3};\n"
        : "+f"(d[0]), "+f"(d[1]), "+f"(d[2]), "+f"(d[3])
        : "r"(a[0]), "r"(a[1]), "r"(a[2]), "r"(a[3]), "r"(b0), "r"(b1));
}

// Inline BN-affine coefficients from a stats slot (threads t<128 write smem).
// CTYPE 1: relu(bn1(y + fc1_b)) -> a = g*rsqrt(var), s = b - mu*a   (fc bias cancels)
// CTYPE 2: relu(bn3(bn2(y + fc2_b))) -> composed analytically (b2, bn2_b cancel)
template <int CTYPE>
__device__ __forceinline__ void coef_from_slot(int t, int slot,
                                               const float* __restrict__ p0,
                                               const float* __restrict__ p1,
                                               const float* __restrict__ p2,
                                               float* ta_s, float* ts_s) {
    if (t < 128) {
        float mu = g_accs[slot * H + t] * (1.f / NNODE);
        float var = g_accq[slot * H + t] * (1.f / NNODE) - mu * mu;
        if (CTYPE == 1) {
            float a = p0[t] * rsqrtf(var + BN_EPS);
            ta_s[t] = a;
            ts_s[t] = p1[t] - mu * a;
        } else {
            float r2 = rsqrtf(var + BN_EPS);
            float gr = p0[t] * r2;
            float v3 = gr * gr * var;
            float A = gr * p1[t] * rsqrtf(v3 + BN_EPS);
            ta_s[t] = A;
            ts_s[t] = p2[t] - mu * A;
        }
    }
}

// ---------------- weight pre-packing ------------------------------------------
// Matrices 0-3: fc1_w per layer; 4-7: fc2_w per layer; 8: fc_w.
__global__ void packw_k(const float* __restrict__ fc1_w,
                        const float* __restrict__ fc2_w,
                        const float* __restrict__ fc_w) {
    int idx = blockIdx.x * blockDim.x + threadIdx.x;
    if (idx >= 9 * WWORDS) return;
    int m = idx / WWORDS;
    int rem = idx - m * WWORDS;
    int r = rem / SMP, c = rem - r * SMP;
    uint32_t v = 0;
    if (c < 128) {
        const float* src = (m < 4) ? fc1_w + (size_t)m * (H * H)
                         : (m < 8) ? fc2_w + (size_t)(m - 4) * (H * H)
                         : fc_w;
        v = pack_split(src[r * H + c]);
    }
    g_wp[idx] = v;
}

// ---------------- CSR build ---------------------------------------------------
__global__ void zero_k() {
    int i = blockIdx.x * blockDim.x + threadIdx.x;
    if (i < NNODE) g_counts[i] = 0;
    if (i < 8 * H) { g_accs[i] = 0.f; g_accq[i] = 0.f; }
}

__global__ void hist_k(const int* __restrict__ dst) {
    int e = blockIdx.x * blockDim.x + threadIdx.x;
    if (e < NEDGE) atomicAdd(&g_counts[dst[e]], 1);
}

// Decoupled 3-stage scan, all stages full-parallel.
// Stage 1: per-block (1024 counts) reduce -> g_btot.
__global__ void scan1_k() {
    __shared__ int wsum[8];
    int t = threadIdx.x, b = blockIdx.x;
    int4 c = *(const int4*)(g_counts + b * 1024 + t * 4);
    int s = c.x + c.y + c.z + c.w;
    #pragma unroll
    for (int d = 16; d > 0; d >>= 1) s += __shfl_xor_sync(0xffffffffu, s, d);
    if ((t & 31) == 0) wsum[t >> 5] = s;
    __syncthreads();
    if (t == 0) {
        int tot = 0;
        #pragma unroll
        for (int i = 0; i < 8; ++i) tot += wsum[i];
        g_btot[b] = tot;
    }
}

// Stage 2: exclusive scan of the 52 block totals (1 block, 64 threads).
__global__ void scan2_k() {
    __shared__ int sh[64];
    int t = threadIdx.x;
    int v = (t < SCAN_NBLK) ? g_btot[t] : 0;
    sh[t] = v;
    __syncthreads();
    #pragma unroll
    for (int d = 1; d < 64; d <<= 1) {
        int y = (t >= d) ? sh[t - d] : 0;
        __syncthreads();
        sh[t] += y;
        __syncthreads();
    }
    if (t < SCAN_NBLK) g_bbase[t] = sh[t] - v;   // exclusive
}

// Stage 3: block-local exclusive scan + base -> g_offs / g_cursor.
__global__ void scan3_k() {
    __shared__ int wsum[8];
    int t = threadIdx.x, b = blockIdx.x;
    int lane = t & 31, w = t >> 5;
    int i4 = b * 1024 + t * 4;
    int4 c = *(const int4*)(g_counts + i4);
    int s0 = c.x, s1 = s0 + c.y, s2 = s1 + c.z, s3 = s2 + c.w;
    int x = s3;
    #pragma unroll
    for (int d = 1; d < 32; d <<= 1) {
        int y = __shfl_up_sync(0xffffffffu, x, d);
        if (lane >= d) x += y;
    }
    if (lane == 31) wsum[w] = x;
    __syncthreads();
    int wpre = 0;
    #pragma unroll
    for (int i = 0; i < 8; ++i) wpre += (i < w) ? wsum[i] : 0;
    int base = g_bbase[b] + wpre + x - s3;
    if (i4 + 0 < NNODE) { g_offs[i4 + 0] = base;      g_cursor[i4 + 0] = base; }
    if (i4 + 1 < NNODE) { g_offs[i4 + 1] = base + s0; g_cursor[i4 + 1] = base + s0; }
    if (i4 + 2 < NNODE) { g_offs[i4 + 2] = base + s1; g_cursor[i4 + 2] = base + s1; }
    if (i4 + 3 < NNODE) { g_offs[i4 + 3] = base + s2; g_cursor[i4 + 3] = base + s2; }
    if (b == 0 && t == 0) g_offs[NNODE] = NEDGE;
}

__global__ void fill_k(const int* __restrict__ ei) {
    int e = blockIdx.x * blockDim.x + threadIdx.x;
    if (e < NEDGE) {
        int d = ei[NEDGE + e];          // dst row of edge_index [2, E]
        int pos = atomicAdd(&g_cursor[d], 1);
        g_ssrc[pos] = ei[e];            // src
    }
}

// ---------------- aggregation: g_h = T(x_v) + sum_{j in N(v)} T(x_j) ----------
template <bool TRANS>
__global__ __launch_bounds__(256) void agg_k(const float* __restrict__ xext,
                                             int slot_in,
                                             const float* __restrict__ p0,
                                             const float* __restrict__ p1,
                                             const float* __restrict__ p2) {
    __shared__ float ta_s[128], ts_s[128];
    const float* in = TRANS ? (const float*)g_t2 : xext;
    int t = threadIdx.x;

    if (TRANS) {
        coef_from_slot<2>(t, slot_in, p0, p1, p2, ta_s, ts_s);
        __syncthreads();
    }

    int lane = t & 31;
    int node = blockIdx.x * 8 + (t >> 5);
    if (node >= HPAD) return;
    int cb = lane * 4;
    float4* outp = (float4*)(g_h + (size_t)node * H + cb);
    if (node >= NNODE) { *outp = f4zero(); return; }

    float4 Aa = f4zero(), Ss = f4zero();
    if (TRANS) {
        Aa = *(const float4*)(ta_s + cb);
        Ss = *(const float4*)(ts_s + cb);
    }

    float4 a0, a1 = f4zero(), a2 = f4zero(), a3 = f4zero();
    {
        float4 v = *(const float4*)(in + (size_t)node * H + cb);
        a0 = TRANS ? f4affine_relu(v, Aa, Ss) : v;
    }
    int j = g_offs[node];
    int jend = g_offs[node + 1];
    for (; j + 3 < jend; j += 4) {
        int s0 = g_ssrc[j], s1 = g_ssrc[j + 1], s2 = g_ssrc[j + 2], s3 = g_ssrc[j + 3];
        float4 v0 = *(const float4*)(in + (size_t)s0 * H + cb);
        float4 v1 = *(const float4*)(in + (size_t)s1 * H + cb);
        float4 v2 = *(const float4*)(in + (size_t)s2 * H + cb);
        float4 v3 = *(const float4*)(in + (size_t)s3 * H + cb);
        if (TRANS) {
            v0 = f4affine_relu(v0, Aa, Ss); v1 = f4affine_relu(v1, Aa, Ss);
            v2 = f4affine_relu(v2, Aa, Ss); v3 = f4affine_relu(v3, Aa, Ss);
        }
        f4add(a0, v0); f4add(a1, v1); f4add(a2, v2); f4add(a3, v3);
    }
    for (; j < jend; ++j) {
        float4 v = *(const float4*)(in + (size_t)g_ssrc[j] * H + cb);
        if (TRANS) v = f4affine_relu(v, Aa, Ss);
        f4add(a0, v);
    }
    f4add(a0, a1); f4add(a2, a3); f4add(a0, a2);
    *outp = a0;
}

// ---------------- tensor-core GEMM (bf16x3 split, m16n8k16) -------------------
// out[n,o] = sum_k T(A[n,k]) * W[o,k]   BM=64, 2 CTAs/SM.
// 8 warps = 2(m) x 4(n); warp tile m32 x n32.
#define ASZ (64 * SMP)
#define GEMM_SMEM_BYTES ((ASZ + WWORDS + 256) * 4)

template <int CTYPE, bool STATS, bool BIAS>
__global__ __launch_bounds__(256, 2) void gemm_tc(
    int asel, int wsel, float* __restrict__ oext,
    int slot_in, int slot_out,
    const float* __restrict__ p0, const float* __restrict__ p1,
    const float* __restrict__ p2,
    const float* __restrict__ bias, int storeN) {
    const float* A = (asel == 0) ? g_h : (asel == 1) ? g_t1 : g_t2;
    float* out;
    if (BIAS) out = oext;
    else      out = (asel == 0) ? g_t1 : g_t2;

    extern __shared__ uint32_t sm[];
    uint32_t* As = sm;                    // [64][SMP] packed hi|lo
    uint32_t* Ws = sm + ASZ;              // [128][SMP]
    float* ta_s = (float*)(sm + ASZ + WWORDS);
    float* ts_s = ta_s + 128;

    int t = threadIdx.x;
    int m0 = blockIdx.x * 64;

    if (CTYPE != 0) {
        coef_from_slot<CTYPE>(t, slot_in, p0, p1, p2, ta_s, ts_s);
        __syncthreads();
    }

    // ---- W fill: raw copy of pre-packed weights (17 x uint4 per thread) ----
    {
        const uint4* wsrc = (const uint4*)(g_wp + (size_t)wsel * WWORDS);
        uint4* wdst = (uint4*)Ws;
        #pragma unroll
        for (int j = 0; j < 17; ++j) wdst[t + j * 256] = wsrc[t + j * 256];
    }

    // ---- A fill: 8 float4 per thread, optional affine+relu, split-pack ----
    #pragma unroll
    for (int j = 0; j < 8; ++j) {
        int idx = t + j * 256;
        int row = idx >> 5;          // 0..63
        int q = idx & 31;            // float4 index along K
        int gr = m0 + row;
        float4 v = f4zero();
        if (gr < NNODE) {
            v = *(const float4*)(A + (size_t)gr * H + q * 4);
            if (CTYPE != 0) {
                float4 a4 = *(const float4*)(ta_s + q * 4);
                float4 s4 = *(const float4*)(ts_s + q * 4);
                v = f4affine_relu(v, a4, s4);
            }
        }
        *(uint4*)(As + row * SMP + q * 4) = pack_split4(v);
    }
    __syncthreads();

    int lane = t & 31;
    int w = t >> 5;
    int wm = w >> 2;         // m-warp 0..1  (rows wm*32)
    int wn = w & 3;          // n-warp 0..3  (cols wn*32)
    int g = lane >> 2;
    int tig = lane & 3;
    int mb = wm * 32;
    int nb = wn * 32;

    float d[2][4][4];
    #pragma unroll
    for (int mt = 0; mt < 2; ++mt)
        #pragma unroll
        for (int nt = 0; nt < 4; ++nt)
            #pragma unroll
            for (int i = 0; i < 4; ++i) d[mt][nt][i] = 0.f;

    #pragma unroll
    for (int ks = 0; ks < 8; ++ks) {
        int k0 = ks * 16;
        uint32_t ah[2][4], al[2][4];
        #pragma unroll
        for (int mt = 0; mt < 2; ++mt) {
            int r0 = mb + mt * 16 + g;
            uint2 w0 = *(const uint2*)(As + r0 * SMP + k0 + 2 * tig);
            uint2 w1 = *(const uint2*)(As + (r0 + 8) * SMP + k0 + 2 * tig);
            uint2 w2 = *(const uint2*)(As + r0 * SMP + k0 + 8 + 2 * tig);
            uint2 w3 = *(const uint2*)(As + (r0 + 8) * SMP + k0 + 8 + 2 * tig);
            ah[mt][0] = __byte_perm(w0.x, w0.y, 0x5410); al[mt][0] = __byte_perm(w0.x, w0.y, 0x7632);
            ah[mt][1] = __byte_perm(w1.x, w1.y, 0x5410); al[mt][1] = __byte_perm(w1.x, w1.y, 0x7632);
            ah[mt][2] = __byte_perm(w2.x, w2.y, 0x5410); al[mt][2] = __byte_perm(w2.x, w2.y, 0x7632);
            ah[mt][3] = __byte_perm(w3.x, w3.y, 0x5410); al[mt][3] = __byte_perm(w3.x, w3.y, 0x7632);
        }
        #pragma unroll
        for (int nt = 0; nt < 4; ++nt) {
            int o = nb + nt * 8 + g;
            uint2 u0 = *(const uint2*)(Ws + o * SMP + k0 + 2 * tig);
            uint2 u1 = *(const uint2*)(Ws + o * SMP + k0 + 8 + 2 * tig);
            uint32_t bh0 = __byte_perm(u0.x, u0.y, 0x5410);
            uint32_t bl0 = __byte_perm(u0.x, u0.y, 0x7632);
            uint32_t bh1 = __byte_perm(u1.x, u1.y, 0x5410);
            uint32_t bl1 = __byte_perm(u1.x, u1.y, 0x7632);
            #pragma unroll
            for (int mt = 0; mt < 2; ++mt) {
                mma_bf16(d[mt][nt], ah[mt], bh0, bh1);   // hi*hi
                mma_bf16(d[mt][nt], al[mt], bh0, bh1);   // lo*hi
                mma_bf16(d[mt][nt], ah[mt], bl0, bl1);   // hi*lo
            }
        }
    }

    // ---- stats: per-column sum / sumsq (padded rows contribute exact zeros) --
    if (STATS) {
        float s[4][2], q[4][2];
        #pragma unroll
        for (int nt = 0; nt < 4; ++nt)
            #pragma unroll
            for (int j = 0; j < 2; ++j) {
                float sv = 0.f, qv = 0.f;
                #pragma unroll
                for (int mt = 0; mt < 2; ++mt) {
                    float v0 = d[mt][nt][j], v1 = d[mt][nt][j + 2];
                    sv += v0 + v1;
                    qv = fmaf(v0, v0, fmaf(v1, v1, qv));
                }
                #pragma unroll
                for (int off = 4; off < 32; off <<= 1) {
                    sv += __shfl_xor_sync(0xffffffffu, sv, off);
                    qv += __shfl_xor_sync(0xffffffffu, qv, off);
                }
                s[nt][j] = sv; q[nt][j] = qv;
            }
        __syncthreads();                      // done reading As/Ws; reuse as Red
        float* RedS = (float*)sm;             // [8][32]
        float* RedQ = (float*)sm + 256;       // [8][32]
        if (g == 0) {
            #pragma unroll
            for (int nt = 0; nt < 4; ++nt)
                #pragma unroll
                for (int j = 0; j < 2; ++j) {
                    int lc = nt * 8 + tig * 2 + j;
                    RedS[w * 32 + lc] = s[nt][j];
                    RedQ[w * 32 + lc] = q[nt][j];
                }
        }
        __syncthreads();
        if (t < 128) {
            int wn2 = t >> 5;
            int lc = t & 31;
            float sv = RedS[wn2 * 32 + lc] + RedS[(wn2 + 4) * 32 + lc];
            float qv = RedQ[wn2 * 32 + lc] + RedQ[(wn2 + 4) * 32 + lc];
            atomicAdd(&g_accs[slot_out * H + t], sv);
            atomicAdd(&g_accq[slot_out * H + t], qv);
        }
    }

    // ---- store C ----
    #pragma unroll
    for (int nt = 0; nt < 4; ++nt) {
        int col = nb + nt * 8 + tig * 2;
        float2 bb = make_float2(0.f, 0.f);
        if (BIAS) bb = *(const float2*)(bias + col);
        #pragma unroll
        for (int mt = 0; mt < 2; ++mt) {
            int r0 = m0 + mb + mt * 16 + g;
            if (r0 < storeN) {
                float2 v = make_float2(d[mt][nt][0] + bb.x, d[mt][nt][1] + bb.y);
                *(float2*)(out + (size_t)r0 * H + col) = v;
            }
            if (r0 + 8 < storeN) {
                float2 v = make_float2(d[mt][nt][2] + bb.x, d[mt][nt][3] + bb.y);
                *(float2*)(out + (size_t)(r0 + 8) * H + col) = v;
            }
        }
    }
}

// ---------------- launch ------------------------------------------------------
extern "C" void kernel_launch(void* const* d_in, const int* in_sizes, int n_in,
                              void* d_out, int out_size) {
    const float* x     = (const float*)d_in[0];
    const int*   ei    = (const int*)  d_in[1];
    const float* fc1_w = (const float*)d_in[2];
    const float* bn1_g = (const float*)d_in[4];
    const float* bn1_b = (const float*)d_in[5];
    const float* fc2_w = (const float*)d_in[6];
    const float* bn2_g = (const float*)d_in[8];
    const float* bn3_g = (const float*)d_in[10];
    const float* bn3_b = (const float*)d_in[11];
    const float* fc_w  = (const float*)d_in[12];
    const float* fc_b  = (const float*)d_in[13];
    float* out = (float*)d_out;

    cudaFuncSetAttribute(gemm_tc<0, true,  false>,
                         cudaFuncAttributeMaxDynamicSharedMemorySize, GEMM_SMEM_BYTES);
    cudaFuncSetAttribute(gemm_tc<1, true,  false>,
                         cudaFuncAttributeMaxDynamicSharedMemorySize, GEMM_SMEM_BYTES);
    cudaFuncSetAttribute(gemm_tc<2, false, true >,
                         cudaFuncAttributeMaxDynamicSharedMemorySize, GEMM_SMEM_BYTES);

    zero_k<<<(NNODE + 255) / 256, 256>>>();
    packw_k<<<(9 * WWORDS + 255) / 256, 256>>>(fc1_w, fc2_w, fc_w);
    hist_k<<<(NEDGE + 255) / 256, 256>>>(ei + NEDGE);
    scan1_k<<<SCAN_NBLK, 256>>>();
    scan2_k<<<1, 64>>>();
    scan3_k<<<SCAN_NBLK, 256>>>();
    fill_k<<<(NEDGE + 255) / 256, 256>>>(ei);

    const int GEMM_GRID = HPAD / 64;    // 782
    const int AGG_GRID  = HPAD / 8;     // 6256

    for (int i = 0; i < LNUM; ++i) {
        if (i == 0)
            agg_k<false><<<AGG_GRID, 256>>>(x, -1, nullptr, nullptr, nullptr);
        else
            agg_k<true><<<AGG_GRID, 256>>>(nullptr, 2 * i - 1,
                                           bn2_g + (i - 1) * H, bn3_g + (i - 1) * H,
                                           bn3_b + (i - 1) * H);
        // gemm1: g_t1 = g_h @ fc1_w[i]^T, stats -> slot 2i
        gemm_tc<0, true, false><<<GEMM_GRID, 256, GEMM_SMEM_BYTES>>>(
            0, i, nullptr, -1, 2 * i,
            nullptr, nullptr, nullptr, nullptr, HPAD);
        // gemm2: g_t2 = relu(bn1-affine(g_t1)) @ fc2_w[i]^T, stats -> slot 2i+1
        gemm_tc<1, true, false><<<GEMM_GRID, 256, GEMM_SMEM_BYTES>>>(
            1, 4 + i, nullptr, 2 * i, 2 * i + 1,
            bn1_g + i * H, bn1_b + i * H, nullptr, nullptr, HPAD);
    }
    // final classifier: out = relu(bn3∘bn2-affine(g_t2)) @ fc_w^T + fc_b
    gemm_tc<2, false, true><<<GEMM_GRID, 256, GEMM_SMEM_BYTES>>>(
        2, 8, out, 7, -1,
        bn2_g + 3 * H, bn3_g + 3 * H, bn3_b + 3 * H, fc_b, NNODE);
}